// round 15
// baseline (speedup 1.0000x reference)
#include <cuda_runtime.h>
#include <cuda_fp16.h>
#include <mma.h>
#include <cstdint>

#define NN 100000
#define NE 3200000
#define NG 64
#define SCAN_CHUNK 4096
#define NB_SCAN ((NN + SCAN_CHUNK - 1) / SCAN_CHUNK)  // 25
#define EBLK 8

using namespace nvcuda;

// ---------------- scratch (static device globals; no allocation) ----------------
__device__ float g_deg[NN];
__device__ float g_dinv[NN];
__device__ int   g_row_ptr[NN + 1];
__device__ int   g_cur[NN];
__device__ int   g_partials[64];
__device__ int   g_sdst[NE];         // dst per sorted edge
__device__ float2 g_srec[NE];        // .x = src bits, .y = norm
__device__ __half g_w3h[64 * 256];   // W3 pre-converted to fp16
__device__ __half g_xh[NN * 16];
__device__ float g_agg1[NN * 16];
__device__ __half g_h1[NN * 16];
__device__ float g_agg2[NN * 16];
__device__ __half g_h2[NN * 64];
__device__ __half g_agg3h[NN * 64];  // layer-3 aggregation result (fp16)
__device__ float g_sums[NG * 256];
__device__ float g_cnt[NG];

__device__ __forceinline__ float silu(float v) { return v / (1.0f + __expf(-v)); }

__device__ __forceinline__ void redAdd4(float* addr, float a, float b, float c, float d) {
    asm volatile("red.global.add.v4.f32 [%0], {%1,%2,%3,%4};"
                 :: "l"(addr), "f"(a), "f"(b), "f"(c), "f"(d) : "memory");
}

__device__ __forceinline__ uint2 pack4h(float a, float b, float c, float d) {
    __half2 h0 = __floats2half2_rn(a, b);
    __half2 h1 = __floats2half2_rn(c, d);
    uint2 r;
    r.x = *(unsigned*)&h0;
    r.y = *(unsigned*)&h1;
    return r;
}

// ---------------- init: cur=0, deg=1, sums=0, cnt=0, W3 -> fp16 ----------------
__global__ void k_init(int* cur, float* deg, float* sums, float* cnt,
                       const float* __restrict__ W3, __half* w3h, int n) {
    int i = blockIdx.x * blockDim.x + threadIdx.x;
    if (i < n) {
        cur[i] = 0;
        deg[i] = 1.0f;
    }
    if (i < NG * 256) sums[i] = 0.f;
    if (i < NG) cnt[i] = 0.f;
    if (i < 64 * 256 / 4) {
        float4 w = ((const float4*)W3)[i];
        ((uint2*)w3h)[i] = pack4h(w.x, w.y, w.z, w.w);
    }
}

// fused histogram + degree accumulation, ILP 4
__global__ void k_hist_deg(const int* __restrict__ dst, const float* __restrict__ ew,
                           int* cur, float* deg, int e) {
    int i0 = (blockIdx.x * blockDim.x + threadIdx.x) * 4;
    if (i0 + 3 < e) {
        int4 d4 = *(const int4*)&dst[i0];
        float4 w4 = *(const float4*)&ew[i0];
        atomicAdd(&cur[d4.x], 1);
        atomicAdd(&cur[d4.y], 1);
        atomicAdd(&cur[d4.z], 1);
        atomicAdd(&cur[d4.w], 1);
        atomicAdd(&deg[d4.x], w4.x);
        atomicAdd(&deg[d4.y], w4.y);
        atomicAdd(&deg[d4.z], w4.z);
        atomicAdd(&deg[d4.w], w4.w);
    } else {
        for (int i = i0; i < e; i++) {
            atomicAdd(&cur[dst[i]], 1);
            atomicAdd(&deg[dst[i]], ew[i]);
        }
    }
}

__global__ void k_scan1(const int* __restrict__ cnt, int* row_ptr, int* partials, int n) {
    __shared__ int sh[1024];
    int t = threadIdx.x;
    int base = blockIdx.x * SCAN_CHUNK + t * 4;
    int v[4];
    int s = 0;
#pragma unroll
    for (int k = 0; k < 4; k++) {
        int i = base + k;
        v[k] = (i < n) ? cnt[i] : 0;
        s += v[k];
    }
    sh[t] = s;
    __syncthreads();
    for (int off = 1; off < 1024; off <<= 1) {
        int x = (t >= off) ? sh[t - off] : 0;
        __syncthreads();
        sh[t] += x;
        __syncthreads();
    }
    int excl = sh[t] - s;
#pragma unroll
    for (int k = 0; k < 4; k++) {
        int i = base + k;
        if (i < n) row_ptr[i] = excl;
        excl += v[k];
    }
    if (t == 1023) partials[blockIdx.x] = sh[1023];
}

// warp-parallel scan of block partials (nb <= 32)
__global__ void k_scan2(int* partials, int nb, int* row_ptr, int n, int e) {
    int t = threadIdx.x;  // 32
    int v = (t < nb) ? partials[t] : 0;
    int s = v;
#pragma unroll
    for (int off = 1; off < 32; off <<= 1) {
        int x = __shfl_up_sync(0xffffffffu, s, off);
        if (t >= off) s += x;
    }
    if (t < nb) partials[t] = s - v;
    if (t == 0) row_ptr[n] = e;
}

// MERGED node-parallel pass: scan3 fixup + dinv + graph-count + layer-1 seed + fp16 x.
__global__ void k_node(int* row_ptr, int* cur, const int* __restrict__ partials,
                       const float* __restrict__ deg, float* dinv,
                       const int* __restrict__ batch, float* cnt,
                       const float* __restrict__ x, float* agg1, __half* xh, int n) {
    int i = blockIdx.x * blockDim.x + threadIdx.x;
    if (i >= n) return;
    int r = row_ptr[i] + partials[i / SCAN_CHUNK];
    row_ptr[i] = r;
    cur[i] = r;
    float d = rsqrtf(deg[i]);
    dinv[i] = d;
    int g = batch[i];
    unsigned act = __activemask();
    unsigned mask = __match_any_sync(act, g);
    int leader = __ffs(mask) - 1;
    if ((threadIdx.x & 31) == leader) atomicAdd(&cnt[g], (float)__popc(mask));
    float d2 = d * d;
    const float4* X4 = (const float4*)(x + (size_t)i * 16);
    float4* A4 = (float4*)(agg1 + (size_t)i * 16);
    uint2* XH = (uint2*)(xh + (size_t)i * 16);
#pragma unroll
    for (int k = 0; k < 4; k++) {
        float4 v = X4[k];
        float4 o = {v.x * d2, v.y * d2, v.z * d2, v.w * d2};
        A4[k] = o;
        XH[k] = pack4h(v.x, v.y, v.z, v.w);
    }
}

// scatter-fill sorted edge records WITH norm computed inline (12B per edge)
__global__ void k_fill(const int* __restrict__ src, const int* __restrict__ dst,
                       const float* __restrict__ ew, const float* __restrict__ dinv,
                       int* cur, int* sdst, float2* srec, int e) {
    int i = blockIdx.x * blockDim.x + threadIdx.x;
    if (i >= e) return;
    int d = dst[i];
    int s = src[i];
    float nrm = __ldg(&dinv[d]) * ew[i] * __ldg(&dinv[s]);
    int p = atomicAdd(&cur[d], 1);
    sdst[p] = d;
    float2 rec;
    rec.x = __int_as_float(s);
    rec.y = nrm;
    srec[p] = rec;
}

// ---------------- layer 1/2: run-compressed edge scatter (dst-sorted, fp16 gather) --
__global__ void k_scatter16h(const int* __restrict__ sdst, const float2* __restrict__ srec,
                             const __half* __restrict__ h, float* agg, int e) {
    int tid = blockIdx.x * blockDim.x + threadIdx.x;
    int blk = tid >> 2;
    int j = tid & 3;
    int e0 = blk * EBLK;
    if (e0 >= e) return;
    int e1 = min(e0 + EBLK, e);
    float4 acc = make_float4(0.f, 0.f, 0.f, 0.f);
    int cur = __ldg(&sdst[e0]);
    for (int ee = e0; ee < e1; ee++) {
        int d = __ldg(&sdst[ee]);
        if (d != cur) {
            redAdd4(agg + (size_t)cur * 16 + j * 4, acc.x, acc.y, acc.z, acc.w);
            acc = make_float4(0.f, 0.f, 0.f, 0.f);
            cur = d;
        }
        float2 rec = __ldg(&srec[ee]);
        int s = __float_as_int(rec.x);
        float w = rec.y;
        uint2 raw = __ldg((const uint2*)h + (size_t)s * 4 + j);
        float2 f0 = __half22float2(*(__half2*)&raw.x);
        float2 f1 = __half22float2(*(__half2*)&raw.y);
        acc.x += w * f0.x;
        acc.y += w * f0.y;
        acc.z += w * f1.x;
        acc.w += w * f1.y;
    }
    redAdd4(agg + (size_t)cur * 16 + j * 4, acc.x, acc.y, acc.z, acc.w);
}

// ---------------- layer 3 gather: warp-per-node CSR, fp16 in/out, ILP8, no atomics --
// seed = h2[node]*dinv^2 in-register; result written fp16 to agg3h.
__global__ void k_agg64h(const int* __restrict__ row_ptr, const float2* __restrict__ srec,
                         const unsigned* __restrict__ h2h, const float* __restrict__ dinv,
                         __half* __restrict__ agg3h, int n) {
    int node = (blockIdx.x * blockDim.x + threadIdx.x) >> 5;
    int lane = threadIdx.x & 31;
    if (node >= n) return;
    int s = row_ptr[node], eN = row_ptr[node + 1];

    unsigned hv = __ldg(&h2h[(size_t)node * 32 + lane]);
    float dv = __ldg(&dinv[node]);
    float d2 = dv * dv;
    float2 fs = __half22float2(*(__half2*)&hv);
    float2 acc[8];
    acc[0] = make_float2(fs.x * d2, fs.y * d2);
#pragma unroll
    for (int k = 1; k < 8; k++) acc[k] = make_float2(0.f, 0.f);

    int e = s;
    for (; e + 7 < eN; e += 8) {
        float2 r[8];
        unsigned v[8];
#pragma unroll
        for (int k = 0; k < 8; k++) r[k] = __ldg(&srec[e + k]);
#pragma unroll
        for (int k = 0; k < 8; k++)
            v[k] = __ldg(&h2h[(size_t)__float_as_int(r[k].x) * 32 + lane]);
#pragma unroll
        for (int k = 0; k < 8; k++) {
            float2 f = __half22float2(*(__half2*)&v[k]);
            acc[k].x += r[k].y * f.x;
            acc[k].y += r[k].y * f.y;
        }
    }
    for (; e + 3 < eN; e += 4) {
        float2 r[4];
        unsigned v[4];
#pragma unroll
        for (int k = 0; k < 4; k++) r[k] = __ldg(&srec[e + k]);
#pragma unroll
        for (int k = 0; k < 4; k++)
            v[k] = __ldg(&h2h[(size_t)__float_as_int(r[k].x) * 32 + lane]);
#pragma unroll
        for (int k = 0; k < 4; k++) {
            float2 f = __half22float2(*(__half2*)&v[k]);
            acc[k].x += r[k].y * f.x;
            acc[k].y += r[k].y * f.y;
        }
    }
    for (; e < eN; e++) {
        float2 r = __ldg(&srec[e]);
        unsigned v = __ldg(&h2h[(size_t)__float_as_int(r.x) * 32 + lane]);
        float2 f = __half22float2(*(__half2*)&v);
        acc[0].x += r.y * f.x;
        acc[0].y += r.y * f.y;
    }
#pragma unroll
    for (int k = 4; k < 8; k++) {
        acc[k - 4].x += acc[k].x;
        acc[k - 4].y += acc[k].y;
    }
    float ox = (acc[0].x + acc[1].x) + (acc[2].x + acc[3].x);
    float oy = (acc[0].y + acc[1].y) + (acc[2].y + acc[3].y);
    ((__half2*)agg3h)[(size_t)node * 32 + lane] = __floats2half2_rn(ox, oy);
}

// ---------------- transforms (layers 1/2) ----------------
// DIN=16, DOUT in {16,64}. h_out(fp16) = silu(agg@W+b); opt aggout = h_out*dinv^2.
template <int DOUT>
__global__ void k_transform16(const float* __restrict__ agg, const float* __restrict__ W,
                              const float* __restrict__ b, const float* __restrict__ dinv,
                              __half* __restrict__ hout, float* __restrict__ aggout, int n) {
    __shared__ float4 sW4[16 * DOUT / 4];
    __shared__ float sB[DOUT];
    int tid = threadIdx.x;
    for (int k = tid; k < 16 * DOUT / 4; k += blockDim.x) sW4[k] = ((const float4*)W)[k];
    for (int k = tid; k < DOUT; k += blockDim.x) sB[k] = b[k];
    __syncthreads();
    int node = blockIdx.x * blockDim.x + tid;
    if (node >= n) return;

    const float4* A4 = (const float4*)(agg + (size_t)node * 16);
    float4 a0 = A4[0], a1 = A4[1], a2 = A4[2], a3 = A4[3];
    float av[16] = {a0.x, a0.y, a0.z, a0.w, a1.x, a1.y, a1.z, a1.w,
                    a2.x, a2.y, a2.z, a2.w, a3.x, a3.y, a3.z, a3.w};

    float4 acc[DOUT / 4];
#pragma unroll
    for (int k = 0; k < DOUT / 4; k++) acc[k] = make_float4(0.f, 0.f, 0.f, 0.f);
#pragma unroll
    for (int i = 0; i < 16; i++) {
#pragma unroll
        for (int k = 0; k < DOUT / 4; k++) {
            float4 w = sW4[i * (DOUT / 4) + k];
            acc[k].x += av[i] * w.x;
            acc[k].y += av[i] * w.y;
            acc[k].z += av[i] * w.z;
            acc[k].w += av[i] * w.w;
        }
    }
    float d = dinv[node];
    float d2 = d * d;
    uint2* H2 = (uint2*)(hout + (size_t)node * DOUT);
    float4* G4 = aggout ? (float4*)(aggout + (size_t)node * DOUT) : nullptr;
#pragma unroll
    for (int k = 0; k < DOUT / 4; k++) {
        float4 v;
        v.x = silu(acc[k].x + sB[4 * k + 0]);
        v.y = silu(acc[k].y + sB[4 * k + 1]);
        v.z = silu(acc[k].z + sB[4 * k + 2]);
        v.w = silu(acc[k].w + sB[4 * k + 3]);
        H2[k] = pack4h(v.x, v.y, v.z, v.w);
        if (G4) {
            float4 g = {v.x * d2, v.y * d2, v.z * d2, v.w * d2};
            G4[k] = g;
        }
    }
}

// DIN=64, DOUT=256 via wmma, fused mean-pool epilogue. A and W already fp16.
__global__ void k_transform64_256_wmma(const __half* __restrict__ agg3h,
                                       const __half* __restrict__ w3h,
                                       const float* __restrict__ b,
                                       const int* __restrict__ batch,
                                       float* __restrict__ sums, int n) {
    extern __shared__ char smem[];
    __half* sA = (__half*)smem;                               // 32*64
    __half* sW = (__half*)(smem + 32 * 64 * 2);               // 64*256
    float* sC = (float*)(smem + 32 * 64 * 2 + 64 * 256 * 2);  // 32*256
    int tid = threadIdx.x;  // 256
    int lane = tid & 31;
    int warp = tid >> 5;
    int nodeBase = blockIdx.x * 32;

    {
        const uint4* Wg = (const uint4*)w3h;
        uint4* Ws = (uint4*)sW;
#pragma unroll
        for (int k = 0; k < 8; k++) Ws[tid + k * 256] = Wg[tid + k * 256];
    }
    {
        const uint4* Ag = (const uint4*)agg3h;
        uint4* As = (uint4*)sA;
        int gi = nodeBase * 8 + tid;
        uint4 z = {0u, 0u, 0u, 0u};
        As[tid] = (gi < n * 8) ? Ag[gi] : z;
    }
    __syncthreads();

    {
        int mt = warp >> 2;
        int nb = (warp & 3) * 64;
        wmma::fragment<wmma::accumulator, 16, 16, 16, float> c[4];
#pragma unroll
        for (int t = 0; t < 4; t++) wmma::fill_fragment(c[t], 0.0f);
#pragma unroll
        for (int kk = 0; kk < 4; kk++) {
            wmma::fragment<wmma::matrix_a, 16, 16, 16, __half, wmma::row_major> af;
            wmma::load_matrix_sync(af, sA + mt * 16 * 64 + kk * 16, 64);
#pragma unroll
            for (int t = 0; t < 4; t++) {
                wmma::fragment<wmma::matrix_b, 16, 16, 16, __half, wmma::row_major> bf;
                wmma::load_matrix_sync(bf, sW + kk * 16 * 256 + nb + t * 16, 256);
                wmma::mma_sync(c[t], af, bf, c[t]);
            }
        }
#pragma unroll
        for (int t = 0; t < 4; t++)
            wmma::store_matrix_sync(sC + mt * 16 * 256 + nb + t * 16, c[t], 256,
                                    wmma::mem_row_major);
    }
    __syncthreads();

    int o0 = lane * 8;
    float bb[8];
#pragma unroll
    for (int k = 0; k < 8; k++) bb[k] = __ldg(&b[o0 + k]);

    int node0 = nodeBase + warp * 4;
    int g0 = (node0 + 0 < n) ? __ldg(&batch[node0 + 0]) : -1;
    int g1 = (node0 + 1 < n) ? __ldg(&batch[node0 + 1]) : -1;
    int g2 = (node0 + 2 < n) ? __ldg(&batch[node0 + 2]) : -1;
    int g3 = (node0 + 3 < n) ? __ldg(&batch[node0 + 3]) : -1;

    float v[4][8];
#pragma unroll
    for (int j = 0; j < 4; j++) {
        const float4* row = (const float4*)(sC + (warp * 4 + j) * 256 + o0);
        float4 r0 = row[0];
        float4 r1 = row[1];
        v[j][0] = silu(r0.x + bb[0]);
        v[j][1] = silu(r0.y + bb[1]);
        v[j][2] = silu(r0.z + bb[2]);
        v[j][3] = silu(r0.w + bb[3]);
        v[j][4] = silu(r1.x + bb[4]);
        v[j][5] = silu(r1.y + bb[5]);
        v[j][6] = silu(r1.z + bb[6]);
        v[j][7] = silu(r1.w + bb[7]);
    }

    if (g0 >= 0 && g0 == g1 && g1 == g2 && g2 == g3) {
        float s[8];
#pragma unroll
        for (int k = 0; k < 8; k++) s[k] = v[0][k] + v[1][k] + v[2][k] + v[3][k];
        float* base = sums + (size_t)g0 * 256 + o0;
        redAdd4(base, s[0], s[1], s[2], s[3]);
        redAdd4(base + 4, s[4], s[5], s[6], s[7]);
    } else {
        int gs[4] = {g0, g1, g2, g3};
#pragma unroll
        for (int j = 0; j < 4; j++) {
            if (gs[j] < 0) continue;
            float* base = sums + (size_t)gs[j] * 256 + o0;
            redAdd4(base, v[j][0], v[j][1], v[j][2], v[j][3]);
            redAdd4(base + 4, v[j][4], v[j][5], v[j][6], v[j][7]);
        }
    }
}

// ---------------- MLP head ----------------
__global__ void k_mlp(const float* __restrict__ sums, const float* __restrict__ cnt,
                      const float* __restrict__ L1, const float* __restrict__ c1,
                      const float* __restrict__ L2, const float* __restrict__ c2,
                      const float* __restrict__ L3, const float* __restrict__ c3,
                      float* __restrict__ out) {
    __shared__ float sp[256];
    __shared__ float s1[128];
    __shared__ float s2[64];
    int g = blockIdx.x;
    int t = threadIdx.x;  // 128
    float invc = 1.0f / fmaxf(cnt[g], 1.0f);
    sp[t] = sums[g * 256 + t] * invc;
    sp[t + 128] = sums[g * 256 + 128 + t] * invc;
    __syncthreads();
    {
        float acc = c1[t];
        for (int i = 0; i < 256; i++) acc += sp[i] * L1[i * 128 + t];
        s1[t] = silu(acc);
    }
    __syncthreads();
    if (t < 64) {
        float acc = c2[t];
        for (int i = 0; i < 128; i++) acc += s1[i] * L2[i * 64 + t];
        s2[t] = silu(acc);
    }
    __syncthreads();
    if (t < 3) {
        float acc = c3[t];
        for (int i = 0; i < 64; i++) acc += s2[i] * L3[i * 3 + t];
        out[g * 3 + t] = acc;
    }
}

// ---------------- launch ----------------
static void* sym(const void* s) {
    void* p = nullptr;
    cudaGetSymbolAddress(&p, s);
    return p;
}

extern "C" void kernel_launch(void* const* d_in, const int* in_sizes, int n_in,
                              void* d_out, int out_size) {
    const float* x = (const float*)d_in[0];
    const int* ei = (const int*)d_in[1];
    const float* ew = (const float*)d_in[2];
    const int* batch = (const int*)d_in[3];
    const float* W1 = (const float*)d_in[4];
    const float* b1 = (const float*)d_in[5];
    const float* W2 = (const float*)d_in[6];
    const float* b2 = (const float*)d_in[7];
    const float* W3 = (const float*)d_in[8];
    const float* b3 = (const float*)d_in[9];
    const float* L1 = (const float*)d_in[10];
    const float* c1 = (const float*)d_in[11];
    const float* L2 = (const float*)d_in[12];
    const float* c2 = (const float*)d_in[13];
    const float* L3 = (const float*)d_in[14];
    const float* c3 = (const float*)d_in[15];
    float* out = (float*)d_out;

    const int N = in_sizes[0] / 16;  // 100000
    const int E = in_sizes[2];       // 3200000
    const int* src = ei;
    const int* dst = ei + E;

    float* deg = (float*)sym(g_deg);
    float* dinv = (float*)sym(g_dinv);
    int* row_ptr = (int*)sym(g_row_ptr);
    int* cur = (int*)sym(g_cur);
    int* partials = (int*)sym(g_partials);
    int* sdst = (int*)sym(g_sdst);
    float2* srec = (float2*)sym(g_srec);
    __half* w3h = (__half*)sym(g_w3h);
    __half* xh = (__half*)sym(g_xh);
    float* agg1 = (float*)sym(g_agg1);
    __half* h1 = (__half*)sym(g_h1);
    float* agg2 = (float*)sym(g_agg2);
    __half* h2 = (__half*)sym(g_h2);
    __half* agg3h = (__half*)sym(g_agg3h);
    float* sums = (float*)sym(g_sums);
    float* cnt = (float*)sym(g_cnt);

    const int T = 256;
    int gn = (N + T - 1) / T;
    int ge = (E + T - 1) / T;
    int ge4 = (E / 4 + T - 1) / T;
    int gw = (N * 32 + T - 1) / T;

    int nblk = (E + EBLK - 1) / EBLK;
    int gs16 = (nblk * 4 + T - 1) / T;

    // preprocessing
    k_init<<<gn, T>>>(cur, deg, sums, cnt, W3, w3h, N);
    k_hist_deg<<<ge4, T>>>(dst, ew, cur, deg, E);
    k_scan1<<<NB_SCAN, 1024>>>(cur, row_ptr, partials, N);
    k_scan2<<<1, 32>>>(partials, NB_SCAN, row_ptr, N, E);
    k_node<<<gn, T>>>(row_ptr, cur, partials, deg, dinv, batch, cnt, x, agg1, xh, N);
    k_fill<<<ge, T>>>(src, dst, ew, dinv, cur, sdst, srec, E);

    // layer 1 (16 -> 16)
    k_scatter16h<<<gs16, T>>>(sdst, srec, xh, agg1, E);
    k_transform16<16><<<gn, T>>>(agg1, W1, b1, dinv, h1, agg2, N);

    // layer 2 (16 -> 64); h2 only (layer-3 seed computed in k_agg64h)
    k_scatter16h<<<gs16, T>>>(sdst, srec, h1, agg2, E);
    k_transform16<64><<<gn, T>>>(agg2, W2, b2, dinv, h2, nullptr, N);

    // layer 3: warp-per-node gather (fp16 out, ILP8), then tensor-core GEMM + fused pool
    k_agg64h<<<gw, T>>>(row_ptr, srec, (const unsigned*)h2, dinv, agg3h, N);
    {
        int smemBytes = 32 * 64 * 2 + 64 * 256 * 2 + 32 * 256 * 4;  // 68KB
        cudaFuncSetAttribute(k_transform64_256_wmma,
                             cudaFuncAttributeMaxDynamicSharedMemorySize, smemBytes);
        int blocks = (N + 31) / 32;
        k_transform64_256_wmma<<<blocks, 256, smemBytes>>>(agg3h, w3h, b3, batch, sums, N);
    }

    // MLP head
    k_mlp<<<NG, 128>>>(sums, cnt, L1, c1, L2, c2, L3, c3, out);
}

// round 16
// speedup vs baseline: 1.0419x; 1.0419x over previous
#include <cuda_runtime.h>
#include <cuda_fp16.h>
#include <mma.h>
#include <cstdint>

#define NN 100000
#define NE 3200000
#define NG 64
#define SCAN_CHUNK 4096
#define NB_SCAN ((NN + SCAN_CHUNK - 1) / SCAN_CHUNK)  // 25
#define EBLK 8

using namespace nvcuda;

// ---------------- scratch (static device globals; no allocation) ----------------
__device__ float g_deg[NN];
__device__ float g_dinv[NN];
__device__ int   g_row_ptr[NN + 1];
__device__ int   g_cur[NN];
__device__ int   g_partials[64];
__device__ int   g_sdst[NE];         // dst per sorted edge
__device__ float2 g_srec[NE];        // .x = src bits, .y = norm
__device__ __half g_w3h[64 * 256];   // W3 pre-converted to fp16
__device__ __half g_xh[NN * 16];
__device__ float g_agg1[NN * 16];
__device__ __half g_h1[NN * 16];
__device__ float g_agg2[NN * 16];
__device__ __half g_h2[NN * 64];
__device__ __half g_agg3h[NN * 64];  // layer-3 aggregation result (fp16)
__device__ float g_sums[NG * 256];
__device__ float g_cnt[NG];

__device__ __forceinline__ float silu(float v) { return v / (1.0f + __expf(-v)); }

__device__ __forceinline__ void redAdd4(float* addr, float a, float b, float c, float d) {
    asm volatile("red.global.add.v4.f32 [%0], {%1,%2,%3,%4};"
                 :: "l"(addr), "f"(a), "f"(b), "f"(c), "f"(d) : "memory");
}

__device__ __forceinline__ uint2 pack4h(float a, float b, float c, float d) {
    __half2 h0 = __floats2half2_rn(a, b);
    __half2 h1 = __floats2half2_rn(c, d);
    uint2 r;
    r.x = *(unsigned*)&h0;
    r.y = *(unsigned*)&h1;
    return r;
}

// ---------------- init: cur=0, deg=1, sums=0, cnt=0, W3 -> fp16 ----------------
__global__ void k_init(int* cur, float* deg, float* sums, float* cnt,
                       const float* __restrict__ W3, __half* w3h, int n) {
    int i = blockIdx.x * blockDim.x + threadIdx.x;
    if (i < n) {
        cur[i] = 0;
        deg[i] = 1.0f;
    }
    if (i < NG * 256) sums[i] = 0.f;
    if (i < NG) cnt[i] = 0.f;
    if (i < 64 * 256 / 4) {
        float4 w = ((const float4*)W3)[i];
        ((uint2*)w3h)[i] = pack4h(w.x, w.y, w.z, w.w);
    }
}

// fused histogram + degree accumulation, ILP 4
__global__ void k_hist_deg(const int* __restrict__ dst, const float* __restrict__ ew,
                           int* cur, float* deg, int e) {
    int i0 = (blockIdx.x * blockDim.x + threadIdx.x) * 4;
    if (i0 + 3 < e) {
        int4 d4 = *(const int4*)&dst[i0];
        float4 w4 = *(const float4*)&ew[i0];
        atomicAdd(&cur[d4.x], 1);
        atomicAdd(&cur[d4.y], 1);
        atomicAdd(&cur[d4.z], 1);
        atomicAdd(&cur[d4.w], 1);
        atomicAdd(&deg[d4.x], w4.x);
        atomicAdd(&deg[d4.y], w4.y);
        atomicAdd(&deg[d4.z], w4.z);
        atomicAdd(&deg[d4.w], w4.w);
    } else {
        for (int i = i0; i < e; i++) {
            atomicAdd(&cur[dst[i]], 1);
            atomicAdd(&deg[dst[i]], ew[i]);
        }
    }
}

__global__ void k_scan1(const int* __restrict__ cnt, int* row_ptr, int* partials, int n) {
    __shared__ int sh[1024];
    int t = threadIdx.x;
    int base = blockIdx.x * SCAN_CHUNK + t * 4;
    int v[4];
    int s = 0;
#pragma unroll
    for (int k = 0; k < 4; k++) {
        int i = base + k;
        v[k] = (i < n) ? cnt[i] : 0;
        s += v[k];
    }
    sh[t] = s;
    __syncthreads();
    for (int off = 1; off < 1024; off <<= 1) {
        int x = (t >= off) ? sh[t - off] : 0;
        __syncthreads();
        sh[t] += x;
        __syncthreads();
    }
    int excl = sh[t] - s;
#pragma unroll
    for (int k = 0; k < 4; k++) {
        int i = base + k;
        if (i < n) row_ptr[i] = excl;
        excl += v[k];
    }
    if (t == 1023) partials[blockIdx.x] = sh[1023];
}

// warp-parallel scan of block partials (nb <= 32)
__global__ void k_scan2(int* partials, int nb, int* row_ptr, int n, int e) {
    int t = threadIdx.x;  // 32
    int v = (t < nb) ? partials[t] : 0;
    int s = v;
#pragma unroll
    for (int off = 1; off < 32; off <<= 1) {
        int x = __shfl_up_sync(0xffffffffu, s, off);
        if (t >= off) s += x;
    }
    if (t < nb) partials[t] = s - v;
    if (t == 0) row_ptr[n] = e;
}

// MERGED node-parallel pass: scan3 fixup + dinv + graph-count + layer-1 seed + fp16 x.
__global__ void k_node(int* row_ptr, int* cur, const int* __restrict__ partials,
                       const float* __restrict__ deg, float* dinv,
                       const int* __restrict__ batch, float* cnt,
                       const float* __restrict__ x, float* agg1, __half* xh, int n) {
    int i = blockIdx.x * blockDim.x + threadIdx.x;
    if (i >= n) return;
    int r = row_ptr[i] + partials[i / SCAN_CHUNK];
    row_ptr[i] = r;
    cur[i] = r;
    float d = rsqrtf(deg[i]);
    dinv[i] = d;
    int g = batch[i];
    unsigned act = __activemask();
    unsigned mask = __match_any_sync(act, g);
    int leader = __ffs(mask) - 1;
    if ((threadIdx.x & 31) == leader) atomicAdd(&cnt[g], (float)__popc(mask));
    float d2 = d * d;
    const float4* X4 = (const float4*)(x + (size_t)i * 16);
    float4* A4 = (float4*)(agg1 + (size_t)i * 16);
    uint2* XH = (uint2*)(xh + (size_t)i * 16);
#pragma unroll
    for (int k = 0; k < 4; k++) {
        float4 v = X4[k];
        float4 o = {v.x * d2, v.y * d2, v.z * d2, v.w * d2};
        A4[k] = o;
        XH[k] = pack4h(v.x, v.y, v.z, v.w);
    }
}

// scatter-fill sorted edge records WITH norm computed inline (12B per edge), ILP 4
__global__ void k_fill(const int* __restrict__ src, const int* __restrict__ dst,
                       const float* __restrict__ ew, const float* __restrict__ dinv,
                       int* cur, int* sdst, float2* srec, int e) {
    int i0 = (blockIdx.x * blockDim.x + threadIdx.x) * 4;
    if (i0 + 3 < e) {
        int4 s4 = *(const int4*)&src[i0];
        int4 d4 = *(const int4*)&dst[i0];
        float4 w4 = *(const float4*)&ew[i0];
        float ds0 = __ldg(&dinv[s4.x]), ds1 = __ldg(&dinv[s4.y]),
              ds2 = __ldg(&dinv[s4.z]), ds3 = __ldg(&dinv[s4.w]);
        float dd0 = __ldg(&dinv[d4.x]), dd1 = __ldg(&dinv[d4.y]),
              dd2 = __ldg(&dinv[d4.z]), dd3 = __ldg(&dinv[d4.w]);
        int p0 = atomicAdd(&cur[d4.x], 1);
        int p1 = atomicAdd(&cur[d4.y], 1);
        int p2 = atomicAdd(&cur[d4.z], 1);
        int p3 = atomicAdd(&cur[d4.w], 1);
        sdst[p0] = d4.x;
        sdst[p1] = d4.y;
        sdst[p2] = d4.z;
        sdst[p3] = d4.w;
        float2 r0 = {__int_as_float(s4.x), dd0 * w4.x * ds0};
        float2 r1 = {__int_as_float(s4.y), dd1 * w4.y * ds1};
        float2 r2 = {__int_as_float(s4.z), dd2 * w4.z * ds2};
        float2 r3 = {__int_as_float(s4.w), dd3 * w4.w * ds3};
        srec[p0] = r0;
        srec[p1] = r1;
        srec[p2] = r2;
        srec[p3] = r3;
    } else {
        for (int i = i0; i < e; i++) {
            int d = dst[i];
            int s = src[i];
            float nrm = __ldg(&dinv[d]) * ew[i] * __ldg(&dinv[s]);
            int p = atomicAdd(&cur[d], 1);
            sdst[p] = d;
            float2 rec;
            rec.x = __int_as_float(s);
            rec.y = nrm;
            srec[p] = rec;
        }
    }
}

// ---------------- layer 1/2: run-compressed edge scatter (dst-sorted, fp16 gather) --
__global__ void k_scatter16h(const int* __restrict__ sdst, const float2* __restrict__ srec,
                             const __half* __restrict__ h, float* agg, int e) {
    int tid = blockIdx.x * blockDim.x + threadIdx.x;
    int blk = tid >> 2;
    int j = tid & 3;
    int e0 = blk * EBLK;
    if (e0 >= e) return;
    int e1 = min(e0 + EBLK, e);
    float4 acc = make_float4(0.f, 0.f, 0.f, 0.f);
    int cur = __ldg(&sdst[e0]);
    for (int ee = e0; ee < e1; ee++) {
        int d = __ldg(&sdst[ee]);
        if (d != cur) {
            redAdd4(agg + (size_t)cur * 16 + j * 4, acc.x, acc.y, acc.z, acc.w);
            acc = make_float4(0.f, 0.f, 0.f, 0.f);
            cur = d;
        }
        float2 rec = __ldg(&srec[ee]);
        int s = __float_as_int(rec.x);
        float w = rec.y;
        uint2 raw = __ldg((const uint2*)h + (size_t)s * 4 + j);
        float2 f0 = __half22float2(*(__half2*)&raw.x);
        float2 f1 = __half22float2(*(__half2*)&raw.y);
        acc.x += w * f0.x;
        acc.y += w * f0.y;
        acc.z += w * f1.x;
        acc.w += w * f1.y;
    }
    redAdd4(agg + (size_t)cur * 16 + j * 4, acc.x, acc.y, acc.z, acc.w);
}

// ---------------- layer 3 gather: warp-per-node CSR, fp16 in/out, ILP4, no atomics --
// seed = h2[node]*dinv^2 in-register; result written fp16 to agg3h.
__global__ void k_agg64h(const int* __restrict__ row_ptr, const float2* __restrict__ srec,
                         const unsigned* __restrict__ h2h, const float* __restrict__ dinv,
                         __half* __restrict__ agg3h, int n) {
    int node = (blockIdx.x * blockDim.x + threadIdx.x) >> 5;
    int lane = threadIdx.x & 31;
    if (node >= n) return;
    int s = row_ptr[node], eN = row_ptr[node + 1];

    unsigned hv = __ldg(&h2h[(size_t)node * 32 + lane]);
    float dv = __ldg(&dinv[node]);
    float d2 = dv * dv;
    float2 f = __half22float2(*(__half2*)&hv);
    float2 acc0 = {f.x * d2, f.y * d2};
    float2 acc1 = {0.f, 0.f}, acc2 = {0.f, 0.f}, acc3 = {0.f, 0.f};

    int e = s;
    for (; e + 3 < eN; e += 4) {
        float2 r0 = __ldg(&srec[e + 0]);
        float2 r1 = __ldg(&srec[e + 1]);
        float2 r2 = __ldg(&srec[e + 2]);
        float2 r3 = __ldg(&srec[e + 3]);
        unsigned v0 = __ldg(&h2h[(size_t)__float_as_int(r0.x) * 32 + lane]);
        unsigned v1 = __ldg(&h2h[(size_t)__float_as_int(r1.x) * 32 + lane]);
        unsigned v2 = __ldg(&h2h[(size_t)__float_as_int(r2.x) * 32 + lane]);
        unsigned v3 = __ldg(&h2h[(size_t)__float_as_int(r3.x) * 32 + lane]);
        float2 f0 = __half22float2(*(__half2*)&v0);
        float2 f1 = __half22float2(*(__half2*)&v1);
        float2 f2 = __half22float2(*(__half2*)&v2);
        float2 f3 = __half22float2(*(__half2*)&v3);
        acc0.x += r0.y * f0.x;
        acc0.y += r0.y * f0.y;
        acc1.x += r1.y * f1.x;
        acc1.y += r1.y * f1.y;
        acc2.x += r2.y * f2.x;
        acc2.y += r2.y * f2.y;
        acc3.x += r3.y * f3.x;
        acc3.y += r3.y * f3.y;
    }
    for (; e < eN; e++) {
        float2 r = __ldg(&srec[e]);
        unsigned v = __ldg(&h2h[(size_t)__float_as_int(r.x) * 32 + lane]);
        float2 fv = __half22float2(*(__half2*)&v);
        acc0.x += r.y * fv.x;
        acc0.y += r.y * fv.y;
    }
    float ox = (acc0.x + acc1.x) + (acc2.x + acc3.x);
    float oy = (acc0.y + acc1.y) + (acc2.y + acc3.y);
    ((__half2*)agg3h)[(size_t)node * 32 + lane] = __floats2half2_rn(ox, oy);
}

// ---------------- transforms (layers 1/2) ----------------
// DIN=16, DOUT in {16,64}. h_out(fp16) = silu(agg@W+b); opt aggout = h_out*dinv^2.
template <int DOUT>
__global__ void k_transform16(const float* __restrict__ agg, const float* __restrict__ W,
                              const float* __restrict__ b, const float* __restrict__ dinv,
                              __half* __restrict__ hout, float* __restrict__ aggout, int n) {
    __shared__ float4 sW4[16 * DOUT / 4];
    __shared__ float sB[DOUT];
    int tid = threadIdx.x;
    for (int k = tid; k < 16 * DOUT / 4; k += blockDim.x) sW4[k] = ((const float4*)W)[k];
    for (int k = tid; k < DOUT; k += blockDim.x) sB[k] = b[k];
    __syncthreads();
    int node = blockIdx.x * blockDim.x + tid;
    if (node >= n) return;

    const float4* A4 = (const float4*)(agg + (size_t)node * 16);
    float4 a0 = A4[0], a1 = A4[1], a2 = A4[2], a3 = A4[3];
    float av[16] = {a0.x, a0.y, a0.z, a0.w, a1.x, a1.y, a1.z, a1.w,
                    a2.x, a2.y, a2.z, a2.w, a3.x, a3.y, a3.z, a3.w};

    float4 acc[DOUT / 4];
#pragma unroll
    for (int k = 0; k < DOUT / 4; k++) acc[k] = make_float4(0.f, 0.f, 0.f, 0.f);
#pragma unroll
    for (int i = 0; i < 16; i++) {
#pragma unroll
        for (int k = 0; k < DOUT / 4; k++) {
            float4 w = sW4[i * (DOUT / 4) + k];
            acc[k].x += av[i] * w.x;
            acc[k].y += av[i] * w.y;
            acc[k].z += av[i] * w.z;
            acc[k].w += av[i] * w.w;
        }
    }
    float d = dinv[node];
    float d2 = d * d;
    uint2* H2 = (uint2*)(hout + (size_t)node * DOUT);
    float4* G4 = aggout ? (float4*)(aggout + (size_t)node * DOUT) : nullptr;
#pragma unroll
    for (int k = 0; k < DOUT / 4; k++) {
        float4 v;
        v.x = silu(acc[k].x + sB[4 * k + 0]);
        v.y = silu(acc[k].y + sB[4 * k + 1]);
        v.z = silu(acc[k].z + sB[4 * k + 2]);
        v.w = silu(acc[k].w + sB[4 * k + 3]);
        H2[k] = pack4h(v.x, v.y, v.z, v.w);
        if (G4) {
            float4 g = {v.x * d2, v.y * d2, v.z * d2, v.w * d2};
            G4[k] = g;
        }
    }
}

// DIN=64, DOUT=256 via wmma, fused mean-pool epilogue. A and W already fp16.
__global__ void k_transform64_256_wmma(const __half* __restrict__ agg3h,
                                       const __half* __restrict__ w3h,
                                       const float* __restrict__ b,
                                       const int* __restrict__ batch,
                                       float* __restrict__ sums, int n) {
    extern __shared__ char smem[];
    __half* sA = (__half*)smem;                               // 32*64
    __half* sW = (__half*)(smem + 32 * 64 * 2);               // 64*256
    float* sC = (float*)(smem + 32 * 64 * 2 + 64 * 256 * 2);  // 32*256
    int tid = threadIdx.x;  // 256
    int lane = tid & 31;
    int warp = tid >> 5;
    int nodeBase = blockIdx.x * 32;

    {
        const uint4* Wg = (const uint4*)w3h;
        uint4* Ws = (uint4*)sW;
#pragma unroll
        for (int k = 0; k < 8; k++) Ws[tid + k * 256] = Wg[tid + k * 256];
    }
    {
        const uint4* Ag = (const uint4*)agg3h;
        uint4* As = (uint4*)sA;
        int gi = nodeBase * 8 + tid;
        uint4 z = {0u, 0u, 0u, 0u};
        As[tid] = (gi < n * 8) ? Ag[gi] : z;
    }
    __syncthreads();

    {
        int mt = warp >> 2;
        int nb = (warp & 3) * 64;
        wmma::fragment<wmma::accumulator, 16, 16, 16, float> c[4];
#pragma unroll
        for (int t = 0; t < 4; t++) wmma::fill_fragment(c[t], 0.0f);
#pragma unroll
        for (int kk = 0; kk < 4; kk++) {
            wmma::fragment<wmma::matrix_a, 16, 16, 16, __half, wmma::row_major> af;
            wmma::load_matrix_sync(af, sA + mt * 16 * 64 + kk * 16, 64);
#pragma unroll
            for (int t = 0; t < 4; t++) {
                wmma::fragment<wmma::matrix_b, 16, 16, 16, __half, wmma::row_major> bf;
                wmma::load_matrix_sync(bf, sW + kk * 16 * 256 + nb + t * 16, 256);
                wmma::mma_sync(c[t], af, bf, c[t]);
            }
        }
#pragma unroll
        for (int t = 0; t < 4; t++)
            wmma::store_matrix_sync(sC + mt * 16 * 256 + nb + t * 16, c[t], 256,
                                    wmma::mem_row_major);
    }
    __syncthreads();

    int o0 = lane * 8;
    float bb[8];
#pragma unroll
    for (int k = 0; k < 8; k++) bb[k] = __ldg(&b[o0 + k]);

    int node0 = nodeBase + warp * 4;
    int g0 = (node0 + 0 < n) ? __ldg(&batch[node0 + 0]) : -1;
    int g1 = (node0 + 1 < n) ? __ldg(&batch[node0 + 1]) : -1;
    int g2 = (node0 + 2 < n) ? __ldg(&batch[node0 + 2]) : -1;
    int g3 = (node0 + 3 < n) ? __ldg(&batch[node0 + 3]) : -1;

    float v[4][8];
#pragma unroll
    for (int j = 0; j < 4; j++) {
        const float4* row = (const float4*)(sC + (warp * 4 + j) * 256 + o0);
        float4 r0 = row[0];
        float4 r1 = row[1];
        v[j][0] = silu(r0.x + bb[0]);
        v[j][1] = silu(r0.y + bb[1]);
        v[j][2] = silu(r0.z + bb[2]);
        v[j][3] = silu(r0.w + bb[3]);
        v[j][4] = silu(r1.x + bb[4]);
        v[j][5] = silu(r1.y + bb[5]);
        v[j][6] = silu(r1.z + bb[6]);
        v[j][7] = silu(r1.w + bb[7]);
    }

    if (g0 >= 0 && g0 == g1 && g1 == g2 && g2 == g3) {
        float s[8];
#pragma unroll
        for (int k = 0; k < 8; k++) s[k] = v[0][k] + v[1][k] + v[2][k] + v[3][k];
        float* base = sums + (size_t)g0 * 256 + o0;
        redAdd4(base, s[0], s[1], s[2], s[3]);
        redAdd4(base + 4, s[4], s[5], s[6], s[7]);
    } else {
        int gs[4] = {g0, g1, g2, g3};
#pragma unroll
        for (int j = 0; j < 4; j++) {
            if (gs[j] < 0) continue;
            float* base = sums + (size_t)gs[j] * 256 + o0;
            redAdd4(base, v[j][0], v[j][1], v[j][2], v[j][3]);
            redAdd4(base + 4, v[j][4], v[j][5], v[j][6], v[j][7]);
        }
    }
}

// ---------------- MLP head ----------------
__global__ void k_mlp(const float* __restrict__ sums, const float* __restrict__ cnt,
                      const float* __restrict__ L1, const float* __restrict__ c1,
                      const float* __restrict__ L2, const float* __restrict__ c2,
                      const float* __restrict__ L3, const float* __restrict__ c3,
                      float* __restrict__ out) {
    __shared__ float sp[256];
    __shared__ float s1[128];
    __shared__ float s2[64];
    int g = blockIdx.x;
    int t = threadIdx.x;  // 128
    float invc = 1.0f / fmaxf(cnt[g], 1.0f);
    sp[t] = sums[g * 256 + t] * invc;
    sp[t + 128] = sums[g * 256 + 128 + t] * invc;
    __syncthreads();
    {
        float acc = c1[t];
        for (int i = 0; i < 256; i++) acc += sp[i] * L1[i * 128 + t];
        s1[t] = silu(acc);
    }
    __syncthreads();
    if (t < 64) {
        float acc = c2[t];
        for (int i = 0; i < 128; i++) acc += s1[i] * L2[i * 64 + t];
        s2[t] = silu(acc);
    }
    __syncthreads();
    if (t < 3) {
        float acc = c3[t];
        for (int i = 0; i < 64; i++) acc += s2[i] * L3[i * 3 + t];
        out[g * 3 + t] = acc;
    }
}

// ---------------- launch ----------------
static void* sym(const void* s) {
    void* p = nullptr;
    cudaGetSymbolAddress(&p, s);
    return p;
}

extern "C" void kernel_launch(void* const* d_in, const int* in_sizes, int n_in,
                              void* d_out, int out_size) {
    const float* x = (const float*)d_in[0];
    const int* ei = (const int*)d_in[1];
    const float* ew = (const float*)d_in[2];
    const int* batch = (const int*)d_in[3];
    const float* W1 = (const float*)d_in[4];
    const float* b1 = (const float*)d_in[5];
    const float* W2 = (const float*)d_in[6];
    const float* b2 = (const float*)d_in[7];
    const float* W3 = (const float*)d_in[8];
    const float* b3 = (const float*)d_in[9];
    const float* L1 = (const float*)d_in[10];
    const float* c1 = (const float*)d_in[11];
    const float* L2 = (const float*)d_in[12];
    const float* c2 = (const float*)d_in[13];
    const float* L3 = (const float*)d_in[14];
    const float* c3 = (const float*)d_in[15];
    float* out = (float*)d_out;

    const int N = in_sizes[0] / 16;  // 100000
    const int E = in_sizes[2];       // 3200000
    const int* src = ei;
    const int* dst = ei + E;

    float* deg = (float*)sym(g_deg);
    float* dinv = (float*)sym(g_dinv);
    int* row_ptr = (int*)sym(g_row_ptr);
    int* cur = (int*)sym(g_cur);
    int* partials = (int*)sym(g_partials);
    int* sdst = (int*)sym(g_sdst);
    float2* srec = (float2*)sym(g_srec);
    __half* w3h = (__half*)sym(g_w3h);
    __half* xh = (__half*)sym(g_xh);
    float* agg1 = (float*)sym(g_agg1);
    __half* h1 = (__half*)sym(g_h1);
    float* agg2 = (float*)sym(g_agg2);
    __half* h2 = (__half*)sym(g_h2);
    __half* agg3h = (__half*)sym(g_agg3h);
    float* sums = (float*)sym(g_sums);
    float* cnt = (float*)sym(g_cnt);

    const int T = 256;
    int gn = (N + T - 1) / T;
    int ge4 = (E / 4 + T - 1) / T;
    int gw = (N * 32 + T - 1) / T;

    int nblk = (E + EBLK - 1) / EBLK;
    int gs16 = (nblk * 4 + T - 1) / T;

    // preprocessing
    k_init<<<gn, T>>>(cur, deg, sums, cnt, W3, w3h, N);
    k_hist_deg<<<ge4, T>>>(dst, ew, cur, deg, E);
    k_scan1<<<NB_SCAN, 1024>>>(cur, row_ptr, partials, N);
    k_scan2<<<1, 32>>>(partials, NB_SCAN, row_ptr, N, E);
    k_node<<<gn, T>>>(row_ptr, cur, partials, deg, dinv, batch, cnt, x, agg1, xh, N);
    k_fill<<<ge4, T>>>(src, dst, ew, dinv, cur, sdst, srec, E);

    // layer 1 (16 -> 16)
    k_scatter16h<<<gs16, T>>>(sdst, srec, xh, agg1, E);
    k_transform16<16><<<gn, T>>>(agg1, W1, b1, dinv, h1, agg2, N);

    // layer 2 (16 -> 64); h2 only (layer-3 seed computed in k_agg64h)
    k_scatter16h<<<gs16, T>>>(sdst, srec, h1, agg2, E);
    k_transform16<64><<<gn, T>>>(agg2, W2, b2, dinv, h2, nullptr, N);

    // layer 3: warp-per-node gather (fp16 out, ILP4), then tensor-core GEMM + fused pool
    k_agg64h<<<gw, T>>>(row_ptr, srec, (const unsigned*)h2, dinv, agg3h, N);
    {
        int smemBytes = 32 * 64 * 2 + 64 * 256 * 2 + 32 * 256 * 4;  // 68KB
        cudaFuncSetAttribute(k_transform64_256_wmma,
                             cudaFuncAttributeMaxDynamicSharedMemorySize, smemBytes);
        int blocks = (N + 31) / 32;
        k_transform64_256_wmma<<<blocks, 256, smemBytes>>>(agg3h, w3h, b3, batch, sums, N);
    }

    // MLP head
    k_mlp<<<NG, 128>>>(sums, cnt, L1, c1, L2, c2, L3, c3, out);
}

// round 17
// speedup vs baseline: 1.0671x; 1.0242x over previous
#include <cuda_runtime.h>
#include <cuda_fp16.h>
#include <mma.h>
#include <cstdint>

#define NN 100000
#define NE 3200000
#define NG 64
#define SCAN_CHUNK 4096
#define NB_SCAN ((NN + SCAN_CHUNK - 1) / SCAN_CHUNK)  // 25
#define EBLK 8

using namespace nvcuda;

// ---------------- scratch (static device globals; no allocation) ----------------
__device__ float g_deg[NN];
__device__ float g_dinv[NN];
__device__ int   g_row_ptr[NN + 1];
__device__ int   g_cur[NN];
__device__ int   g_partials[64];
__device__ int   g_sdst[NE];         // dst per sorted edge
__device__ float2 g_srec[NE];        // .x = src bits, .y = norm
__device__ __half g_w3h[64 * 256];   // W3 pre-converted to fp16
__device__ __half g_xh[NN * 16];
__device__ float g_agg1[NN * 16];
__device__ __half g_h1[NN * 16];
__device__ float g_agg2[NN * 16];
__device__ __half g_h2[NN * 64];
__device__ __half g_agg3h[NN * 64];  // layer-3 aggregation result (fp16)
__device__ float g_sums[NG * 256];
__device__ float g_cnt[NG];

__device__ __forceinline__ float silu(float v) { return v / (1.0f + __expf(-v)); }

__device__ __forceinline__ void redAdd4(float* addr, float a, float b, float c, float d) {
    asm volatile("red.global.add.v4.f32 [%0], {%1,%2,%3,%4};"
                 :: "l"(addr), "f"(a), "f"(b), "f"(c), "f"(d) : "memory");
}

__device__ __forceinline__ uint2 pack4h(float a, float b, float c, float d) {
    __half2 h0 = __floats2half2_rn(a, b);
    __half2 h1 = __floats2half2_rn(c, d);
    uint2 r;
    r.x = *(unsigned*)&h0;
    r.y = *(unsigned*)&h1;
    return r;
}

// ---------------- init: cur=0, deg=1, sums=0, cnt=0, W3 -> fp16 ----------------
__global__ void k_init(int* cur, float* deg, float* sums, float* cnt,
                       const float* __restrict__ W3, __half* w3h, int n) {
    int i = blockIdx.x * blockDim.x + threadIdx.x;
    if (i < n) {
        cur[i] = 0;
        deg[i] = 1.0f;
    }
    if (i < NG * 256) sums[i] = 0.f;
    if (i < NG) cnt[i] = 0.f;
    if (i < 64 * 256 / 4) {
        float4 w = ((const float4*)W3)[i];
        ((uint2*)w3h)[i] = pack4h(w.x, w.y, w.z, w.w);
    }
}

// fused histogram + degree accumulation, ILP 4
__global__ void k_hist_deg(const int* __restrict__ dst, const float* __restrict__ ew,
                           int* cur, float* deg, int e) {
    int i0 = (blockIdx.x * blockDim.x + threadIdx.x) * 4;
    if (i0 + 3 < e) {
        int4 d4 = *(const int4*)&dst[i0];
        float4 w4 = *(const float4*)&ew[i0];
        atomicAdd(&cur[d4.x], 1);
        atomicAdd(&cur[d4.y], 1);
        atomicAdd(&cur[d4.z], 1);
        atomicAdd(&cur[d4.w], 1);
        atomicAdd(&deg[d4.x], w4.x);
        atomicAdd(&deg[d4.y], w4.y);
        atomicAdd(&deg[d4.z], w4.z);
        atomicAdd(&deg[d4.w], w4.w);
    } else {
        for (int i = i0; i < e; i++) {
            atomicAdd(&cur[dst[i]], 1);
            atomicAdd(&deg[dst[i]], ew[i]);
        }
    }
}

__global__ void k_scan1(const int* __restrict__ cnt, int* row_ptr, int* partials, int n) {
    __shared__ int sh[1024];
    int t = threadIdx.x;
    int base = blockIdx.x * SCAN_CHUNK + t * 4;
    int v[4];
    int s = 0;
#pragma unroll
    for (int k = 0; k < 4; k++) {
        int i = base + k;
        v[k] = (i < n) ? cnt[i] : 0;
        s += v[k];
    }
    sh[t] = s;
    __syncthreads();
    for (int off = 1; off < 1024; off <<= 1) {
        int x = (t >= off) ? sh[t - off] : 0;
        __syncthreads();
        sh[t] += x;
        __syncthreads();
    }
    int excl = sh[t] - s;
#pragma unroll
    for (int k = 0; k < 4; k++) {
        int i = base + k;
        if (i < n) row_ptr[i] = excl;
        excl += v[k];
    }
    if (t == 1023) partials[blockIdx.x] = sh[1023];
}

// warp-parallel scan of block partials (nb <= 32)
__global__ void k_scan2(int* partials, int nb, int* row_ptr, int n, int e) {
    int t = threadIdx.x;  // 32
    int v = (t < nb) ? partials[t] : 0;
    int s = v;
#pragma unroll
    for (int off = 1; off < 32; off <<= 1) {
        int x = __shfl_up_sync(0xffffffffu, s, off);
        if (t >= off) s += x;
    }
    if (t < nb) partials[t] = s - v;
    if (t == 0) row_ptr[n] = e;
}

// MERGED node-parallel pass: scan3 fixup + dinv + graph-count + layer-1 seed + fp16 x.
__global__ void k_node(int* row_ptr, int* cur, const int* __restrict__ partials,
                       const float* __restrict__ deg, float* dinv,
                       const int* __restrict__ batch, float* cnt,
                       const float* __restrict__ x, float* agg1, __half* xh, int n) {
    int i = blockIdx.x * blockDim.x + threadIdx.x;
    if (i >= n) return;
    int r = row_ptr[i] + partials[i / SCAN_CHUNK];
    row_ptr[i] = r;
    cur[i] = r;
    float d = rsqrtf(deg[i]);
    dinv[i] = d;
    int g = batch[i];
    unsigned act = __activemask();
    unsigned mask = __match_any_sync(act, g);
    int leader = __ffs(mask) - 1;
    if ((threadIdx.x & 31) == leader) atomicAdd(&cnt[g], (float)__popc(mask));
    float d2 = d * d;
    const float4* X4 = (const float4*)(x + (size_t)i * 16);
    float4* A4 = (float4*)(agg1 + (size_t)i * 16);
    uint2* XH = (uint2*)(xh + (size_t)i * 16);
#pragma unroll
    for (int k = 0; k < 4; k++) {
        float4 v = X4[k];
        float4 o = {v.x * d2, v.y * d2, v.z * d2, v.w * d2};
        A4[k] = o;
        XH[k] = pack4h(v.x, v.y, v.z, v.w);
    }
}

// scatter-fill sorted edge records WITH norm computed inline (12B per edge)
__global__ void k_fill(const int* __restrict__ src, const int* __restrict__ dst,
                       const float* __restrict__ ew, const float* __restrict__ dinv,
                       int* cur, int* sdst, float2* srec, int e) {
    int i = blockIdx.x * blockDim.x + threadIdx.x;
    if (i >= e) return;
    int d = dst[i];
    int s = src[i];
    float nrm = __ldg(&dinv[d]) * ew[i] * __ldg(&dinv[s]);
    int p = atomicAdd(&cur[d], 1);
    sdst[p] = d;
    float2 rec;
    rec.x = __int_as_float(s);
    rec.y = nrm;
    srec[p] = rec;
}

// ---------------- layer 1/2: run-compressed edge scatter (dst-sorted, fp16 gather) --
// Vectorized batch-prefetch: full 8-edge blocks load sdst (2x int4), srec (4x float4)
// and all 8 h-row gathers up front (MLP=8), then run the compare/flush chain on regs.
__global__ void k_scatter16h(const int* __restrict__ sdst, const float2* __restrict__ srec,
                             const __half* __restrict__ h, float* agg, int e) {
    int tid = blockIdx.x * blockDim.x + threadIdx.x;
    int blk = tid >> 2;
    int j = tid & 3;
    int e0 = blk * EBLK;
    if (e0 >= e) return;

    if (e0 + EBLK <= e) {
        int4 da = *(const int4*)&sdst[e0];
        int4 db = *(const int4*)&sdst[e0 + 4];
        int ds[8] = {da.x, da.y, da.z, da.w, db.x, db.y, db.z, db.w};
        float4 sa = *(const float4*)&srec[e0];
        float4 sb = *(const float4*)&srec[e0 + 2];
        float4 sc = *(const float4*)&srec[e0 + 4];
        float4 sd = *(const float4*)&srec[e0 + 6];
        float2 rec[8] = {{sa.x, sa.y}, {sa.z, sa.w}, {sb.x, sb.y}, {sb.z, sb.w},
                         {sc.x, sc.y}, {sc.z, sc.w}, {sd.x, sd.y}, {sd.z, sd.w}};
        uint2 raw[8];
#pragma unroll
        for (int k = 0; k < 8; k++)
            raw[k] = __ldg((const uint2*)h + (size_t)__float_as_int(rec[k].x) * 4 + j);

        float4 acc = make_float4(0.f, 0.f, 0.f, 0.f);
        int cur = ds[0];
#pragma unroll
        for (int k = 0; k < 8; k++) {
            if (ds[k] != cur) {
                redAdd4(agg + (size_t)cur * 16 + j * 4, acc.x, acc.y, acc.z, acc.w);
                acc = make_float4(0.f, 0.f, 0.f, 0.f);
                cur = ds[k];
            }
            float w = rec[k].y;
            float2 f0 = __half22float2(*(__half2*)&raw[k].x);
            float2 f1 = __half22float2(*(__half2*)&raw[k].y);
            acc.x += w * f0.x;
            acc.y += w * f0.y;
            acc.z += w * f1.x;
            acc.w += w * f1.y;
        }
        redAdd4(agg + (size_t)cur * 16 + j * 4, acc.x, acc.y, acc.z, acc.w);
    } else {
        // scalar tail
        int e1 = e;
        float4 acc = make_float4(0.f, 0.f, 0.f, 0.f);
        int cur = __ldg(&sdst[e0]);
        for (int ee = e0; ee < e1; ee++) {
            int d = __ldg(&sdst[ee]);
            if (d != cur) {
                redAdd4(agg + (size_t)cur * 16 + j * 4, acc.x, acc.y, acc.z, acc.w);
                acc = make_float4(0.f, 0.f, 0.f, 0.f);
                cur = d;
            }
            float2 rec = __ldg(&srec[ee]);
            int s = __float_as_int(rec.x);
            float w = rec.y;
            uint2 raw = __ldg((const uint2*)h + (size_t)s * 4 + j);
            float2 f0 = __half22float2(*(__half2*)&raw.x);
            float2 f1 = __half22float2(*(__half2*)&raw.y);
            acc.x += w * f0.x;
            acc.y += w * f0.y;
            acc.z += w * f1.x;
            acc.w += w * f1.y;
        }
        redAdd4(agg + (size_t)cur * 16 + j * 4, acc.x, acc.y, acc.z, acc.w);
    }
}

// ---------------- layer 3 gather: warp-per-node CSR, fp16 in/out, ILP4, no atomics --
// seed = h2[node]*dinv^2 in-register; result written fp16 to agg3h.
__global__ void k_agg64h(const int* __restrict__ row_ptr, const float2* __restrict__ srec,
                         const unsigned* __restrict__ h2h, const float* __restrict__ dinv,
                         __half* __restrict__ agg3h, int n) {
    int node = (blockIdx.x * blockDim.x + threadIdx.x) >> 5;
    int lane = threadIdx.x & 31;
    if (node >= n) return;
    int s = row_ptr[node], eN = row_ptr[node + 1];

    unsigned hv = __ldg(&h2h[(size_t)node * 32 + lane]);
    float dv = __ldg(&dinv[node]);
    float d2 = dv * dv;
    float2 f = __half22float2(*(__half2*)&hv);
    float2 acc0 = {f.x * d2, f.y * d2};
    float2 acc1 = {0.f, 0.f}, acc2 = {0.f, 0.f}, acc3 = {0.f, 0.f};

    int e = s;
    for (; e + 3 < eN; e += 4) {
        float2 r0 = __ldg(&srec[e + 0]);
        float2 r1 = __ldg(&srec[e + 1]);
        float2 r2 = __ldg(&srec[e + 2]);
        float2 r3 = __ldg(&srec[e + 3]);
        unsigned v0 = __ldg(&h2h[(size_t)__float_as_int(r0.x) * 32 + lane]);
        unsigned v1 = __ldg(&h2h[(size_t)__float_as_int(r1.x) * 32 + lane]);
        unsigned v2 = __ldg(&h2h[(size_t)__float_as_int(r2.x) * 32 + lane]);
        unsigned v3 = __ldg(&h2h[(size_t)__float_as_int(r3.x) * 32 + lane]);
        float2 f0 = __half22float2(*(__half2*)&v0);
        float2 f1 = __half22float2(*(__half2*)&v1);
        float2 f2 = __half22float2(*(__half2*)&v2);
        float2 f3 = __half22float2(*(__half2*)&v3);
        acc0.x += r0.y * f0.x;
        acc0.y += r0.y * f0.y;
        acc1.x += r1.y * f1.x;
        acc1.y += r1.y * f1.y;
        acc2.x += r2.y * f2.x;
        acc2.y += r2.y * f2.y;
        acc3.x += r3.y * f3.x;
        acc3.y += r3.y * f3.y;
    }
    for (; e < eN; e++) {
        float2 r = __ldg(&srec[e]);
        unsigned v = __ldg(&h2h[(size_t)__float_as_int(r.x) * 32 + lane]);
        float2 fv = __half22float2(*(__half2*)&v);
        acc0.x += r.y * fv.x;
        acc0.y += r.y * fv.y;
    }
    float ox = (acc0.x + acc1.x) + (acc2.x + acc3.x);
    float oy = (acc0.y + acc1.y) + (acc2.y + acc3.y);
    ((__half2*)agg3h)[(size_t)node * 32 + lane] = __floats2half2_rn(ox, oy);
}

// ---------------- transforms (layers 1/2) ----------------
// DIN=16, DOUT in {16,64}. h_out(fp16) = silu(agg@W+b); opt aggout = h_out*dinv^2.
template <int DOUT>
__global__ void k_transform16(const float* __restrict__ agg, const float* __restrict__ W,
                              const float* __restrict__ b, const float* __restrict__ dinv,
                              __half* __restrict__ hout, float* __restrict__ aggout, int n) {
    __shared__ float4 sW4[16 * DOUT / 4];
    __shared__ float sB[DOUT];
    int tid = threadIdx.x;
    for (int k = tid; k < 16 * DOUT / 4; k += blockDim.x) sW4[k] = ((const float4*)W)[k];
    for (int k = tid; k < DOUT; k += blockDim.x) sB[k] = b[k];
    __syncthreads();
    int node = blockIdx.x * blockDim.x + tid;
    if (node >= n) return;

    const float4* A4 = (const float4*)(agg + (size_t)node * 16);
    float4 a0 = A4[0], a1 = A4[1], a2 = A4[2], a3 = A4[3];
    float av[16] = {a0.x, a0.y, a0.z, a0.w, a1.x, a1.y, a1.z, a1.w,
                    a2.x, a2.y, a2.z, a2.w, a3.x, a3.y, a3.z, a3.w};

    float4 acc[DOUT / 4];
#pragma unroll
    for (int k = 0; k < DOUT / 4; k++) acc[k] = make_float4(0.f, 0.f, 0.f, 0.f);
#pragma unroll
    for (int i = 0; i < 16; i++) {
#pragma unroll
        for (int k = 0; k < DOUT / 4; k++) {
            float4 w = sW4[i * (DOUT / 4) + k];
            acc[k].x += av[i] * w.x;
            acc[k].y += av[i] * w.y;
            acc[k].z += av[i] * w.z;
            acc[k].w += av[i] * w.w;
        }
    }
    float d = dinv[node];
    float d2 = d * d;
    uint2* H2 = (uint2*)(hout + (size_t)node * DOUT);
    float4* G4 = aggout ? (float4*)(aggout + (size_t)node * DOUT) : nullptr;
#pragma unroll
    for (int k = 0; k < DOUT / 4; k++) {
        float4 v;
        v.x = silu(acc[k].x + sB[4 * k + 0]);
        v.y = silu(acc[k].y + sB[4 * k + 1]);
        v.z = silu(acc[k].z + sB[4 * k + 2]);
        v.w = silu(acc[k].w + sB[4 * k + 3]);
        H2[k] = pack4h(v.x, v.y, v.z, v.w);
        if (G4) {
            float4 g = {v.x * d2, v.y * d2, v.z * d2, v.w * d2};
            G4[k] = g;
        }
    }
}

// DIN=64, DOUT=256 via wmma, fused mean-pool epilogue. A and W already fp16.
__global__ void k_transform64_256_wmma(const __half* __restrict__ agg3h,
                                       const __half* __restrict__ w3h,
                                       const float* __restrict__ b,
                                       const int* __restrict__ batch,
                                       float* __restrict__ sums, int n) {
    extern __shared__ char smem[];
    __half* sA = (__half*)smem;                               // 32*64
    __half* sW = (__half*)(smem + 32 * 64 * 2);               // 64*256
    float* sC = (float*)(smem + 32 * 64 * 2 + 64 * 256 * 2);  // 32*256
    int tid = threadIdx.x;  // 256
    int lane = tid & 31;
    int warp = tid >> 5;
    int nodeBase = blockIdx.x * 32;

    {
        const uint4* Wg = (const uint4*)w3h;
        uint4* Ws = (uint4*)sW;
#pragma unroll
        for (int k = 0; k < 8; k++) Ws[tid + k * 256] = Wg[tid + k * 256];
    }
    {
        const uint4* Ag = (const uint4*)agg3h;
        uint4* As = (uint4*)sA;
        int gi = nodeBase * 8 + tid;
        uint4 z = {0u, 0u, 0u, 0u};
        As[tid] = (gi < n * 8) ? Ag[gi] : z;
    }
    __syncthreads();

    {
        int mt = warp >> 2;
        int nb = (warp & 3) * 64;
        wmma::fragment<wmma::accumulator, 16, 16, 16, float> c[4];
#pragma unroll
        for (int t = 0; t < 4; t++) wmma::fill_fragment(c[t], 0.0f);
#pragma unroll
        for (int kk = 0; kk < 4; kk++) {
            wmma::fragment<wmma::matrix_a, 16, 16, 16, __half, wmma::row_major> af;
            wmma::load_matrix_sync(af, sA + mt * 16 * 64 + kk * 16, 64);
#pragma unroll
            for (int t = 0; t < 4; t++) {
                wmma::fragment<wmma::matrix_b, 16, 16, 16, __half, wmma::row_major> bf;
                wmma::load_matrix_sync(bf, sW + kk * 16 * 256 + nb + t * 16, 256);
                wmma::mma_sync(c[t], af, bf, c[t]);
            }
        }
#pragma unroll
        for (int t = 0; t < 4; t++)
            wmma::store_matrix_sync(sC + mt * 16 * 256 + nb + t * 16, c[t], 256,
                                    wmma::mem_row_major);
    }
    __syncthreads();

    int o0 = lane * 8;
    float bb[8];
#pragma unroll
    for (int k = 0; k < 8; k++) bb[k] = __ldg(&b[o0 + k]);

    int node0 = nodeBase + warp * 4;
    int g0 = (node0 + 0 < n) ? __ldg(&batch[node0 + 0]) : -1;
    int g1 = (node0 + 1 < n) ? __ldg(&batch[node0 + 1]) : -1;
    int g2 = (node0 + 2 < n) ? __ldg(&batch[node0 + 2]) : -1;
    int g3 = (node0 + 3 < n) ? __ldg(&batch[node0 + 3]) : -1;

    float v[4][8];
#pragma unroll
    for (int j = 0; j < 4; j++) {
        const float4* row = (const float4*)(sC + (warp * 4 + j) * 256 + o0);
        float4 r0 = row[0];
        float4 r1 = row[1];
        v[j][0] = silu(r0.x + bb[0]);
        v[j][1] = silu(r0.y + bb[1]);
        v[j][2] = silu(r0.z + bb[2]);
        v[j][3] = silu(r0.w + bb[3]);
        v[j][4] = silu(r1.x + bb[4]);
        v[j][5] = silu(r1.y + bb[5]);
        v[j][6] = silu(r1.z + bb[6]);
        v[j][7] = silu(r1.w + bb[7]);
    }

    if (g0 >= 0 && g0 == g1 && g1 == g2 && g2 == g3) {
        float s[8];
#pragma unroll
        for (int k = 0; k < 8; k++) s[k] = v[0][k] + v[1][k] + v[2][k] + v[3][k];
        float* base = sums + (size_t)g0 * 256 + o0;
        redAdd4(base, s[0], s[1], s[2], s[3]);
        redAdd4(base + 4, s[4], s[5], s[6], s[7]);
    } else {
        int gs[4] = {g0, g1, g2, g3};
#pragma unroll
        for (int j = 0; j < 4; j++) {
            if (gs[j] < 0) continue;
            float* base = sums + (size_t)gs[j] * 256 + o0;
            redAdd4(base, v[j][0], v[j][1], v[j][2], v[j][3]);
            redAdd4(base + 4, v[j][4], v[j][5], v[j][6], v[j][7]);
        }
    }
}

// ---------------- MLP head ----------------
__global__ void k_mlp(const float* __restrict__ sums, const float* __restrict__ cnt,
                      const float* __restrict__ L1, const float* __restrict__ c1,
                      const float* __restrict__ L2, const float* __restrict__ c2,
                      const float* __restrict__ L3, const float* __restrict__ c3,
                      float* __restrict__ out) {
    __shared__ float sp[256];
    __shared__ float s1[128];
    __shared__ float s2[64];
    int g = blockIdx.x;
    int t = threadIdx.x;  // 128
    float invc = 1.0f / fmaxf(cnt[g], 1.0f);
    sp[t] = sums[g * 256 + t] * invc;
    sp[t + 128] = sums[g * 256 + 128 + t] * invc;
    __syncthreads();
    {
        float acc = c1[t];
        for (int i = 0; i < 256; i++) acc += sp[i] * L1[i * 128 + t];
        s1[t] = silu(acc);
    }
    __syncthreads();
    if (t < 64) {
        float acc = c2[t];
        for (int i = 0; i < 128; i++) acc += s1[i] * L2[i * 64 + t];
        s2[t] = silu(acc);
    }
    __syncthreads();
    if (t < 3) {
        float acc = c3[t];
        for (int i = 0; i < 64; i++) acc += s2[i] * L3[i * 3 + t];
        out[g * 3 + t] = acc;
    }
}

// ---------------- launch ----------------
static void* sym(const void* s) {
    void* p = nullptr;
    cudaGetSymbolAddress(&p, s);
    return p;
}

extern "C" void kernel_launch(void* const* d_in, const int* in_sizes, int n_in,
                              void* d_out, int out_size) {
    const float* x = (const float*)d_in[0];
    const int* ei = (const int*)d_in[1];
    const float* ew = (const float*)d_in[2];
    const int* batch = (const int*)d_in[3];
    const float* W1 = (const float*)d_in[4];
    const float* b1 = (const float*)d_in[5];
    const float* W2 = (const float*)d_in[6];
    const float* b2 = (const float*)d_in[7];
    const float* W3 = (const float*)d_in[8];
    const float* b3 = (const float*)d_in[9];
    const float* L1 = (const float*)d_in[10];
    const float* c1 = (const float*)d_in[11];
    const float* L2 = (const float*)d_in[12];
    const float* c2 = (const float*)d_in[13];
    const float* L3 = (const float*)d_in[14];
    const float* c3 = (const float*)d_in[15];
    float* out = (float*)d_out;

    const int N = in_sizes[0] / 16;  // 100000
    const int E = in_sizes[2];       // 3200000
    const int* src = ei;
    const int* dst = ei + E;

    float* deg = (float*)sym(g_deg);
    float* dinv = (float*)sym(g_dinv);
    int* row_ptr = (int*)sym(g_row_ptr);
    int* cur = (int*)sym(g_cur);
    int* partials = (int*)sym(g_partials);
    int* sdst = (int*)sym(g_sdst);
    float2* srec = (float2*)sym(g_srec);
    __half* w3h = (__half*)sym(g_w3h);
    __half* xh = (__half*)sym(g_xh);
    float* agg1 = (float*)sym(g_agg1);
    __half* h1 = (__half*)sym(g_h1);
    float* agg2 = (float*)sym(g_agg2);
    __half* h2 = (__half*)sym(g_h2);
    __half* agg3h = (__half*)sym(g_agg3h);
    float* sums = (float*)sym(g_sums);
    float* cnt = (float*)sym(g_cnt);

    const int T = 256;
    int gn = (N + T - 1) / T;
    int ge = (E + T - 1) / T;
    int ge4 = (E / 4 + T - 1) / T;
    int gw = (N * 32 + T - 1) / T;

    int nblk = (E + EBLK - 1) / EBLK;
    int gs16 = (nblk * 4 + T - 1) / T;

    // preprocessing
    k_init<<<gn, T>>>(cur, deg, sums, cnt, W3, w3h, N);
    k_hist_deg<<<ge4, T>>>(dst, ew, cur, deg, E);
    k_scan1<<<NB_SCAN, 1024>>>(cur, row_ptr, partials, N);
    k_scan2<<<1, 32>>>(partials, NB_SCAN, row_ptr, N, E);
    k_node<<<gn, T>>>(row_ptr, cur, partials, deg, dinv, batch, cnt, x, agg1, xh, N);
    k_fill<<<ge, T>>>(src, dst, ew, dinv, cur, sdst, srec, E);

    // layer 1 (16 -> 16)
    k_scatter16h<<<gs16, T>>>(sdst, srec, xh, agg1, E);
    k_transform16<16><<<gn, T>>>(agg1, W1, b1, dinv, h1, agg2, N);

    // layer 2 (16 -> 64); h2 only (layer-3 seed computed in k_agg64h)
    k_scatter16h<<<gs16, T>>>(sdst, srec, h1, agg2, E);
    k_transform16<64><<<gn, T>>>(agg2, W2, b2, dinv, h2, nullptr, N);

    // layer 3: warp-per-node gather (fp16 out, ILP4), then tensor-core GEMM + fused pool
    k_agg64h<<<gw, T>>>(row_ptr, srec, (const unsigned*)h2, dinv, agg3h, N);
    {
        int smemBytes = 32 * 64 * 2 + 64 * 256 * 2 + 32 * 256 * 4;  // 68KB
        cudaFuncSetAttribute(k_transform64_256_wmma,
                             cudaFuncAttributeMaxDynamicSharedMemorySize, smemBytes);
        int blocks = (N + 31) / 32;
        k_transform64_256_wmma<<<blocks, 256, smemBytes>>>(agg3h, w3h, b3, batch, sums, N);
    }

    // MLP head
    k_mlp<<<NG, 128>>>(sums, cnt, L1, c1, L2, c2, L3, c3, out);
}